// round 1
// baseline (speedup 1.0000x reference)
#include <cuda_runtime.h>

// B=4096, T=256, F=64, H=16 (4H=64), D=64
// Warp = 8 rows = 4 row-pairs. lane = p*8 + j ; p = pair (0..3), j = col group (0..7).
// Thread computes gate columns [8j, 8j+8) for its pair, packed f32x2 over (rowA,rowB).

typedef unsigned long long ull;

__device__ __forceinline__ ull fma2(ull a, ull b, ull c) {
    ull d;
    asm("fma.rn.f32x2 %0, %1, %2, %3;" : "=l"(d) : "l"(a), "l"(b), "l"(c));
    return d;
}
__device__ __forceinline__ ull d2u(double d) { return (ull)__double_as_longlong(d); }
__device__ __forceinline__ double u2d(ull u) { return __longlong_as_double((long long)u); }
__device__ __forceinline__ float sigf(float z) {
    return __fdividef(1.0f, 1.0f + __expf(-z));
}
// Swizzled float2 offset within a 64-wide duplicated-weight row so that the
// 4 chunk loads (LDS.128) of thread j land at byte offset i*128 + j*16:
// col c -> f2 index 16*((c&7)>>1) + 2*(c>>3) + (c&1)
__device__ __forceinline__ int soff(int c) {
    return (((c & 7) >> 1) << 4) + ((c >> 3) << 1) + (c & 1);
}

__global__ void __launch_bounds__(128, 1) lstm_kernel(
    const float* __restrict__ x, const float* __restrict__ W,
    const float* __restrict__ U, const float* __restrict__ b,
    const float* __restrict__ Wdn, const float* __restrict__ bdn,
    float* __restrict__ out)
{
    extern __shared__ float2 sm[];
    float2* W2  = sm;            // 64*64 = 4096 f2 (duplicated pairs, swizzled)
    float2* U2  = W2 + 4096;     // 16*64 = 1024
    float2* Wd2 = U2 + 1024;     // 16*64 = 1024
    float2* b2  = Wd2 + 1024;    // 64
    float2* bd2 = b2 + 64;       // 64
    float2* wbase = bd2 + 64;    // 4 warps * 864 f2 each

    const int tid = threadIdx.x;

    // ---- init shared weights (duplicated {w,w}, swizzled) ----
    for (int idx = tid; idx < 4096; idx += 128) {
        int f = idx >> 6, c = idx & 63;
        float w = W[idx];
        W2[f * 64 + soff(c)] = make_float2(w, w);
    }
    for (int idx = tid; idx < 1024; idx += 128) {
        int k = idx >> 6, c = idx & 63;
        float u = U[idx];
        U2[k * 64 + soff(c)] = make_float2(u, u);
        float wd = Wdn[idx];
        Wd2[k * 64 + soff(c)] = make_float2(wd, wd);
    }
    for (int idx = tid; idx < 64; idx += 128) {
        float bv = b[idx];   b2[soff(idx)]  = make_float2(bv, bv);
        float bdv = bdn[idx]; bd2[soff(idx)] = make_float2(bdv, bdv);
    }

    const int warp = tid >> 5, lane = tid & 31;
    float2* wreg = wbase + warp * 864;
    float2* xb0 = wreg;          // 4 pairs * 66 = 264 f2 (padded stride 66)
    float2* xb1 = wreg + 264;    // 264
    float2* zw  = wreg + 528;    // 264
    float2* h2  = wreg + 792;    // 4 pairs * 18 = 72

    for (int i = lane; i < 72; i += 32) h2[i] = make_float2(0.f, 0.f);
    __syncthreads();

    const int p = lane >> 3, j = lane & 7;
    const int rowBase = blockIdx.x * 32 + warp * 8;
    const int rA = rowBase + 2 * p;
    const float* xA = x + (size_t)rA * 256 * 64;
    const float* xB = xA + (size_t)256 * 64;
    const int fr = j * 8;

    // ---- stage t = 0 (interleaved {A,B} pairs) ----
    {
        float4 a0 = *(const float4*)(xA + fr);
        float4 a1 = *(const float4*)(xA + fr + 4);
        float4 c0 = *(const float4*)(xB + fr);
        float4 c1 = *(const float4*)(xB + fr + 4);
        float4* xw = (float4*)(xb0 + p * 66 + fr);
        xw[0] = make_float4(a0.x, c0.x, a0.y, c0.y);
        xw[1] = make_float4(a0.z, c0.z, a0.w, c0.w);
        xw[2] = make_float4(a1.x, c1.x, a1.y, c1.y);
        xw[3] = make_float4(a1.z, c1.z, a1.w, c1.w);
    }
    __syncwarp();

    float2 cr0 = make_float2(0.f, 0.f), cr1 = make_float2(0.f, 0.f);
    const float2* xc = xb0;
    float2* xn = xb1;

#pragma unroll 1
    for (int t = 0; t < 256; t++) {
        // prefetch x(t+1) into registers (clamped at tail)
        const int tp = (t < 255) ? t + 1 : 255;
        float4 pa0 = *(const float4*)(xA + tp * 64 + fr);
        float4 pa1 = *(const float4*)(xA + tp * 64 + fr + 4);
        float4 pb0 = *(const float4*)(xB + tp * 64 + fr);
        float4 pb1 = *(const float4*)(xB + tp * 64 + fr + 4);

        // acc = bias
        ull acc[8];
        {
            const double2* br = (const double2*)b2;
#pragma unroll
            for (int i = 0; i < 4; i++) {
                double2 v = br[i * 8 + j];
                acc[2 * i] = d2u(v.x);
                acc[2 * i + 1] = d2u(v.y);
            }
        }
        // z += x_t @ W   (packed over row pair)
        const double* xdp = (const double*)(xc + p * 66);
#pragma unroll
        for (int f = 0; f < 64; f++) {
            ull xv = d2u(xdp[f]);
            const double2* wr = (const double2*)(W2 + f * 64);
#pragma unroll
            for (int i = 0; i < 4; i++) {
                double2 w = wr[i * 8 + j];
                acc[2 * i]     = fma2(xv, d2u(w.x), acc[2 * i]);
                acc[2 * i + 1] = fma2(xv, d2u(w.y), acc[2 * i + 1]);
            }
        }
        // z += h_{t-1} @ U
        const double* hdp = (const double*)(h2 + p * 18);
#pragma unroll
        for (int k = 0; k < 16; k++) {
            ull hv = d2u(hdp[k]);
            const double2* ur = (const double2*)(U2 + k * 64);
#pragma unroll
            for (int i = 0; i < 4; i++) {
                double2 u = ur[i * 8 + j];
                acc[2 * i]     = fma2(hv, d2u(u.x), acc[2 * i]);
                acc[2 * i + 1] = fma2(hv, d2u(u.y), acc[2 * i + 1]);
            }
        }
        // publish z
        {
            double2* zp = (double2*)(zw + p * 66 + fr);
#pragma unroll
            for (int i = 0; i < 4; i++)
                zp[i] = make_double2(u2d(acc[2 * i]), u2d(acc[2 * i + 1]));
        }
        __syncwarp();

        // gates: this thread owns hidden units k0 = 2j, k0+1 of its pair
        {
            const float2* zr = zw + p * 66;
            const int k0 = 2 * j;
            float2 zi0 = zr[k0],      zi1 = zr[k0 + 1];
            float2 zf0 = zr[16 + k0], zf1 = zr[16 + k0 + 1];
            float2 zg0 = zr[32 + k0], zg1 = zr[32 + k0 + 1];
            float2 zo0 = zr[48 + k0], zo1 = zr[48 + k0 + 1];

            float i0x = sigf(zi0.x), i0y = sigf(zi0.y);
            float i1x = sigf(zi1.x), i1y = sigf(zi1.y);
            float f0x = sigf(zf0.x), f0y = sigf(zf0.y);
            float f1x = sigf(zf1.x), f1y = sigf(zf1.y);
            float g0x = fmaxf(zg0.x, 0.f), g0y = fmaxf(zg0.y, 0.f);
            float g1x = fmaxf(zg1.x, 0.f), g1y = fmaxf(zg1.y, 0.f);
            float o0x = sigf(zo0.x), o0y = sigf(zo0.y);
            float o1x = sigf(zo1.x), o1y = sigf(zo1.y);

            cr0.x = f0x * cr0.x + i0x * g0x;  cr0.y = f0y * cr0.y + i0y * g0y;
            cr1.x = f1x * cr1.x + i1x * g1x;  cr1.y = f1y * cr1.y + i1y * g1y;

            h2[p * 18 + k0]     = make_float2(o0x * fmaxf(cr0.x, 0.f), o0y * fmaxf(cr0.y, 0.f));
            h2[p * 18 + k0 + 1] = make_float2(o1x * fmaxf(cr1.x, 0.f), o1y * fmaxf(cr1.y, 0.f));
        }
        // stage x(t+1)
        {
            float4* xw = (float4*)(xn + p * 66 + fr);
            xw[0] = make_float4(pa0.x, pb0.x, pa0.y, pb0.y);
            xw[1] = make_float4(pa0.z, pb0.z, pa0.w, pb0.w);
            xw[2] = make_float4(pa1.x, pb1.x, pa1.y, pb1.y);
            xw[3] = make_float4(pa1.z, pb1.z, pa1.w, pb1.w);
        }
        __syncwarp();
        float2* tmp = (float2*)xc; xc = xn; xn = tmp;
    }

    // ---- dense: out = normalize(sigmoid(h @ Wd + bd)) ----
    ull acc[8];
    {
        const double2* br = (const double2*)bd2;
#pragma unroll
        for (int i = 0; i < 4; i++) {
            double2 v = br[i * 8 + j];
            acc[2 * i] = d2u(v.x);
            acc[2 * i + 1] = d2u(v.y);
        }
    }
    const double* hdp = (const double*)(h2 + p * 18);
#pragma unroll
    for (int k = 0; k < 16; k++) {
        ull hv = d2u(hdp[k]);
        const double2* wr = (const double2*)(Wd2 + k * 64);
#pragma unroll
        for (int i = 0; i < 4; i++) {
            double2 w = wr[i * 8 + j];
            acc[2 * i]     = fma2(hv, d2u(w.x), acc[2 * i]);
            acc[2 * i + 1] = fma2(hv, d2u(w.y), acc[2 * i + 1]);
        }
    }
    float sA[8], sB[8];
    float sumA = 0.f, sumB = 0.f;
#pragma unroll
    for (int li = 0; li < 8; li++) {
        float vA = __uint_as_float((unsigned)(acc[li] & 0xffffffffull));
        float vB = __uint_as_float((unsigned)(acc[li] >> 32));
        sA[li] = sigf(vA); sB[li] = sigf(vB);
        sumA += sA[li]; sumB += sB[li];
    }
#pragma unroll
    for (int off = 1; off < 8; off <<= 1) {
        sumA += __shfl_xor_sync(0xffffffffu, sumA, off);
        sumB += __shfl_xor_sync(0xffffffffu, sumB, off);
    }
    const float invA = __fdividef(1.f, sumA);
    const float invB = __fdividef(1.f, sumB);
    float* oA = out + (size_t)rA * 64 + fr;
    float* oB = oA + 64;
    *(float4*)oA       = make_float4(sA[0] * invA, sA[1] * invA, sA[2] * invA, sA[3] * invA);
    *(float4*)(oA + 4) = make_float4(sA[4] * invA, sA[5] * invA, sA[6] * invA, sA[7] * invA);
    *(float4*)oB       = make_float4(sB[0] * invB, sB[1] * invB, sB[2] * invB, sB[3] * invB);
    *(float4*)(oB + 4) = make_float4(sB[4] * invB, sB[5] * invB, sB[6] * invB, sB[7] * invB);
}

extern "C" void kernel_launch(void* const* d_in, const int* in_sizes, int n_in,
                              void* d_out, int out_size)
{
    const float* x  = (const float*)d_in[0];
    const float* W  = (const float*)d_in[1];
    const float* U  = (const float*)d_in[2];
    const float* b  = (const float*)d_in[3];
    const float* Wd = (const float*)d_in[4];
    const float* bd = (const float*)d_in[5];
    float* out = (float*)d_out;

    const size_t shmem = 9728 * sizeof(float2);  // 77824 B
    cudaFuncSetAttribute(lstm_kernel, cudaFuncAttributeMaxDynamicSharedMemorySize, (int)shmem);
    lstm_kernel<<<128, 128, shmem>>>(x, W, U, b, Wd, bd, out);
}